// round 5
// baseline (speedup 1.0000x reference)
#include <cuda_runtime.h>
#include <cuda_fp16.h>
#include <math.h>

#define N_V    100000
#define NE_    20000
#define NNZ_   1600000
#define NFEAT_ 128
#define NHID_  64
#define NCLASS_ 40
#define NLAYER_ 4

// ---------------- device scratch (static, no allocation) ----------------
__device__ float g_X [N_V * NHID_];        // current features (fp32 master)
__device__ float g_X0[N_V * NHID_];        // residual anchor (fp32)
__device__ __align__(16) uint4 g_Xh4 [N_V * 8];  // fp16 mirror of X rows (128 B/row)
__device__ __align__(16) uint4 g_Xeh4[NE_ * 8];  // fp16 edge rows (128 B/row)
__device__ float g_escale[NE_];
__device__ int   g_cntE[NE_];
__device__ int   g_cntV[N_V];
__device__ int   g_lenE[NE_];
__device__ int   g_lenV[N_V];
__device__ int   g_offE[NE_];
__device__ int   g_offV[N_V];
__device__ int   g_curE;
__device__ int   g_curV;
__device__ int   g_adjE[NNZ_];             // members (vertex ids) per edge
__device__ int   g_adjV[NNZ_];             // incident edges per vertex

// ---------------- CSR build ----------------
__global__ void zero_cnt_k() {
    int i = blockIdx.x * blockDim.x + threadIdx.x;
    if (i < NE_) g_cntE[i] = 0;
    if (i < N_V) g_cntV[i] = 0;
    if (i == 0) { g_curE = 0; g_curV = 0; }
}

__global__ void hist_k(const int4* __restrict__ vertex4, const int4* __restrict__ edges4) {
    int i = blockIdx.x * blockDim.x + threadIdx.x;
    if (i < NNZ_ / 4) {
        int4 e = edges4[i];
        int4 v = vertex4[i];
        atomicAdd(&g_cntE[e.x], 1);
        atomicAdd(&g_cntE[e.y], 1);
        atomicAdd(&g_cntE[e.z], 1);
        atomicAdd(&g_cntE[e.w], 1);
        atomicAdd(&g_cntV[v.x], 1);
        atomicAdd(&g_cntV[v.y], 1);
        atomicAdd(&g_cntV[v.z], 1);
        atomicAdd(&g_cntV[v.w], 1);
    }
}

// warp-aggregated bump allocation of CSR offsets (segment order arbitrary but
// valid; per-segment sums are order-independent).
__global__ void alloc_k(const float* __restrict__ degE) {
    int i = blockIdx.x * blockDim.x + threadIdx.x;
    const int n = NE_ + N_V;
    if (i >= n) return;           // NE_ and n are multiples of 32
    int lane = threadIdx.x & 31;
    bool isE = (i < NE_);
    int c = isE ? g_cntE[i] : g_cntV[i - NE_];
    int inc = c;
    #pragma unroll
    for (int o = 1; o < 32; o <<= 1) {
        int t = __shfl_up_sync(0xffffffffu, inc, o);
        if (lane >= o) inc += t;
    }
    int base = 0;
    if (lane == 31)
        base = atomicAdd(isE ? &g_curE : &g_curV, inc);
    base = __shfl_sync(0xffffffffu, base, 31);
    int off = base + inc - c;
    if (isE) {
        g_offE[i] = off;
        g_lenE[i] = c;
        g_escale[i] = degE[i] / fmaxf((float)c, 1.0f);
        g_cntE[i] = 0;
    } else {
        g_offV[i - NE_] = off;
        g_lenV[i - NE_] = c;
        g_cntV[i - NE_] = 0;
    }
}

__global__ void build_adj_k(const int4* __restrict__ vertex4, const int4* __restrict__ edges4) {
    int i = blockIdx.x * blockDim.x + threadIdx.x;
    if (i < NNZ_ / 4) {
        int4 v = vertex4[i];
        int4 e = edges4[i];
        int oe0 = g_offE[e.x], oe1 = g_offE[e.y], oe2 = g_offE[e.z], oe3 = g_offE[e.w];
        int ov0 = g_offV[v.x], ov1 = g_offV[v.y], ov2 = g_offV[v.z], ov3 = g_offV[v.w];
        int pe0 = oe0 + atomicAdd(&g_cntE[e.x], 1);
        int pe1 = oe1 + atomicAdd(&g_cntE[e.y], 1);
        int pe2 = oe2 + atomicAdd(&g_cntE[e.z], 1);
        int pe3 = oe3 + atomicAdd(&g_cntE[e.w], 1);
        int pv0 = ov0 + atomicAdd(&g_cntV[v.x], 1);
        int pv1 = ov1 + atomicAdd(&g_cntV[v.y], 1);
        int pv2 = ov2 + atomicAdd(&g_cntV[v.z], 1);
        int pv3 = ov3 + atomicAdd(&g_cntV[v.w], 1);
        g_adjE[pe0] = v.x; g_adjE[pe1] = v.y; g_adjE[pe2] = v.z; g_adjE[pe3] = v.w;
        g_adjV[pv0] = e.x; g_adjV[pv1] = e.y; g_adjV[pv2] = e.z; g_adjV[pv3] = e.w;
    }
}

// ---------------- vectorized row gather: 4 rows per warp-wide LDG.128 ----------------
// Lane l: row-group g = l>>3 handles rows j + 4u + g; slice s = l&7 covers
// features s*8 .. s*8+7 (16 bytes of the 128-byte fp16 row).
// After the loop, shfl_xor(8,16) merges the 4 row-groups; every lane holds the
// summed 8-feature slice for its s.
__device__ __forceinline__ void gather_rows(const uint4* __restrict__ src,
    const int* __restrict__ adj, int beg, int len, int lane, float acc[8])
{
    int g = lane >> 3, s = lane & 7;
    for (int jj = 0; jj < len; jj += 16) {
        int t = jj + (lane & 15);
        int idx = 0;
        if (t < len) idx = adj[beg + t];            // 16 indices, coalesced
        #pragma unroll
        for (int u = 0; u < 4; u++) {
            int r = (u << 2) + g;                   // row within this 16-group
            int ridx = __shfl_sync(0xffffffffu, idx, r);
            if (jj + r < len) {
                uint4 q = __ldg(src + ridx * 8 + s);
                float2 f0 = __half22float2(*(__half2*)&q.x);
                float2 f1 = __half22float2(*(__half2*)&q.y);
                float2 f2 = __half22float2(*(__half2*)&q.z);
                float2 f3 = __half22float2(*(__half2*)&q.w);
                acc[0] += f0.x; acc[1] += f0.y; acc[2] += f1.x; acc[3] += f1.y;
                acc[4] += f2.x; acc[5] += f2.y; acc[6] += f3.x; acc[7] += f3.y;
            }
        }
    }
    #pragma unroll
    for (int i = 0; i < 8; i++) {
        acc[i] += __shfl_xor_sync(0xffffffffu, acc[i], 8);
        acc[i] += __shfl_xor_sync(0xffffffffu, acc[i], 16);
    }
}

// ---------------- vertex -> edge mean (warp per edge) ----------------
__global__ void __launch_bounds__(256) agg_ve_k() {
    int e = blockIdx.x * 8 + (threadIdx.x >> 5);
    if (e >= NE_) return;
    int lane = threadIdx.x & 31;
    float acc[8] = {0.f, 0.f, 0.f, 0.f, 0.f, 0.f, 0.f, 0.f};
    gather_rows(g_Xh4, g_adjE, g_offE[e], g_lenE[e], lane, acc);
    if ((lane >> 3) == 0) {                        // lanes 0..7 store the row
        int s = lane & 7;
        float sc = g_escale[e];
        __half2 h0 = __floats2half2_rn(acc[0] * sc, acc[1] * sc);
        __half2 h1 = __floats2half2_rn(acc[2] * sc, acc[3] * sc);
        __half2 h2 = __floats2half2_rn(acc[4] * sc, acc[5] * sc);
        __half2 h3 = __floats2half2_rn(acc[6] * sc, acc[7] * sc);
        uint4 q;
        q.x = *(unsigned*)&h0; q.y = *(unsigned*)&h1;
        q.z = *(unsigned*)&h2; q.w = *(unsigned*)&h3;
        g_Xeh4[e * 8 + s] = q;
    }
}

// ---------------- edge -> vertex sum (warp per vertex), fused *degV,
//                  L2 norm (shuffle-only), alpha-mix -> fp32 Xi ----------------
__global__ void __launch_bounds__(256) agg_ev_k(const float* __restrict__ degV) {
    int v = blockIdx.x * 8 + (threadIdx.x >> 5);
    if (v >= N_V) return;
    int lane = threadIdx.x & 31;
    float acc[8] = {0.f, 0.f, 0.f, 0.f, 0.f, 0.f, 0.f, 0.f};
    gather_rows(g_Xeh4, g_adjV, g_offV[v], g_lenV[v], lane, acc);

    float dv = __ldg(&degV[v]);
    float ss = 0.f;
    #pragma unroll
    for (int i = 0; i < 8; i++) { acc[i] *= dv; ss += acc[i] * acc[i]; }
    // sum across the 8 feature slices (groups already merged, so xor 1/2/4 suffices)
    ss += __shfl_xor_sync(0xffffffffu, ss, 1);
    ss += __shfl_xor_sync(0xffffffffu, ss, 2);
    ss += __shfl_xor_sync(0xffffffffu, ss, 4);
    float sc = (ss > 0.f) ? rsqrtf(ss) : 0.f;

    if ((lane >> 3) == 0) {                        // lanes 0..7 write fp32 row
        int s = lane & 7;
        const float4* x0p = (const float4*)&g_X0[(size_t)v * NHID_ + s * 8];
        float4 xa = x0p[0], xb = x0p[1];
        float4 ra, rb;
        ra.x = 0.9f * acc[0] * sc + 0.1f * xa.x;
        ra.y = 0.9f * acc[1] * sc + 0.1f * xa.y;
        ra.z = 0.9f * acc[2] * sc + 0.1f * xa.z;
        ra.w = 0.9f * acc[3] * sc + 0.1f * xa.w;
        rb.x = 0.9f * acc[4] * sc + 0.1f * xb.x;
        rb.y = 0.9f * acc[5] * sc + 0.1f * xb.y;
        rb.z = 0.9f * acc[6] * sc + 0.1f * xb.z;
        rb.w = 0.9f * acc[7] * sc + 0.1f * xb.w;
        float4* xp = (float4*)&g_X[(size_t)v * NHID_ + s * 8];
        xp[0] = ra; xp[1] = rb;
    }
}

// ---------------- tiled GEMM (64 rows x NCOL), K chunked by 64 ----------------
// MODE 0: X = relu(A@W + b) -> g_X, g_X0, g_Xh.   (A = external x, K=128, NCOL=64)
// MODE 1: X = relu(c0*Xi + c1*(Xi@W)) -> g_X, g_Xh. (K=NCOL=64)
// MODE 2: out = log_softmax(g_X@W + b).            (K=64, NCOL=40)
template <int K, int NCOL, int MODE>
__global__ void __launch_bounds__(256) gemm_k(
    const float* __restrict__ Aext, const float* __restrict__ W,
    const float* __restrict__ bias, float* __restrict__ outext,
    float c0, float c1)
{
    constexpr int KC = 64;
    constexpr int KP = KC + 4;
    constexpr int NP = (NCOL + 7) & ~3;
    __shared__ float As[64 * KP];
    __shared__ float Wsm[KC * NP];
    __shared__ float Ls[(MODE == 2) ? 64 * NCOL : 1];

    const float* A = (MODE == 0) ? Aext : g_X;
    const int M = N_V;
    int tid = threadIdx.x;
    int row0 = blockIdx.x * 64;
    int tx = tid & 15, ty = tid >> 4;
    bool active = (NCOL == 64) || (tx * 4 < NCOL);

    float acc[4][4] = {};

    for (int kc = 0; kc < K; kc += KC) {
        for (int idx = tid; idx < KC * NCOL; idx += 256) {
            int k = idx / NCOL, c = idx - k * NCOL;
            Wsm[k * NP + c] = W[(kc + k) * NCOL + c];
        }
        for (int idx = tid; idx < 64 * KC; idx += 256) {
            int r = idx >> 6, k = idx & 63;
            int row = row0 + r;
            As[r * KP + k] = (row < M) ? A[(size_t)row * K + kc + k] : 0.f;
        }
        __syncthreads();
        if (active) {
            #pragma unroll 8
            for (int k = 0; k < KC; k++) {
                float4 w = *(const float4*)&Wsm[k * NP + tx * 4];
                float a0 = As[(ty * 4 + 0) * KP + k];
                float a1 = As[(ty * 4 + 1) * KP + k];
                float a2 = As[(ty * 4 + 2) * KP + k];
                float a3 = As[(ty * 4 + 3) * KP + k];
                acc[0][0] += a0 * w.x; acc[0][1] += a0 * w.y; acc[0][2] += a0 * w.z; acc[0][3] += a0 * w.w;
                acc[1][0] += a1 * w.x; acc[1][1] += a1 * w.y; acc[1][2] += a1 * w.z; acc[1][3] += a1 * w.w;
                acc[2][0] += a2 * w.x; acc[2][1] += a2 * w.y; acc[2][2] += a2 * w.z; acc[2][3] += a2 * w.w;
                acc[3][0] += a3 * w.x; acc[3][1] += a3 * w.y; acc[3][2] += a3 * w.z; acc[3][3] += a3 * w.w;
            }
        }
        __syncthreads();
    }

    if (MODE == 0) {
        float bx = __ldg(bias + tx * 4 + 0), by = __ldg(bias + tx * 4 + 1);
        float bz = __ldg(bias + tx * 4 + 2), bw = __ldg(bias + tx * 4 + 3);
        #pragma unroll
        for (int i = 0; i < 4; i++) {
            int row = row0 + ty * 4 + i;
            if (row < M) {
                float4 r4;
                r4.x = fmaxf(acc[i][0] + bx, 0.f);
                r4.y = fmaxf(acc[i][1] + by, 0.f);
                r4.z = fmaxf(acc[i][2] + bz, 0.f);
                r4.w = fmaxf(acc[i][3] + bw, 0.f);
                *(float4*)&g_X [(size_t)row * NHID_ + tx * 4] = r4;
                *(float4*)&g_X0[(size_t)row * NHID_ + tx * 4] = r4;
                __half2 h0 = __floats2half2_rn(r4.x, r4.y);
                __half2 h1 = __floats2half2_rn(r4.z, r4.w);
                uint2 u = make_uint2(*(unsigned*)&h0, *(unsigned*)&h1);
                *(uint2*)((unsigned*)&g_Xh4[row * 8] + tx * 2) = u;
            }
        }
    } else if (MODE == 1) {
        #pragma unroll
        for (int i = 0; i < 4; i++) {
            int r = ty * 4 + i;
            int row = row0 + r;
            if (row < M) {
                float4 r4;
                r4.x = fmaxf(c0 * As[r * KP + tx * 4 + 0] + c1 * acc[i][0], 0.f);
                r4.y = fmaxf(c0 * As[r * KP + tx * 4 + 1] + c1 * acc[i][1], 0.f);
                r4.z = fmaxf(c0 * As[r * KP + tx * 4 + 2] + c1 * acc[i][2], 0.f);
                r4.w = fmaxf(c0 * As[r * KP + tx * 4 + 3] + c1 * acc[i][3], 0.f);
                *(float4*)&g_X[(size_t)row * NHID_ + tx * 4] = r4;
                __half2 h0 = __floats2half2_rn(r4.x, r4.y);
                __half2 h1 = __floats2half2_rn(r4.z, r4.w);
                uint2 u = make_uint2(*(unsigned*)&h0, *(unsigned*)&h1);
                *(uint2*)((unsigned*)&g_Xh4[row * 8] + tx * 2) = u;
            }
        }
    } else {  // MODE 2: logits + fused log_softmax
        if (active) {
            #pragma unroll
            for (int i = 0; i < 4; i++) {
                int r = ty * 4 + i;
                #pragma unroll
                for (int j = 0; j < 4; j++)
                    Ls[r * NCOL + tx * 4 + j] = acc[i][j] + __ldg(bias + tx * 4 + j);
            }
        }
        __syncthreads();
        if (tid < 64) {
            int row = row0 + tid;
            if (row < M) {
                float mx = -1e30f;
                #pragma unroll
                for (int c = 0; c < NCOL; c++) mx = fmaxf(mx, Ls[tid * NCOL + c]);
                float s = 0.f;
                #pragma unroll
                for (int c = 0; c < NCOL; c++) s += __expf(Ls[tid * NCOL + c] - mx);
                float lse = mx + __logf(s);
                #pragma unroll
                for (int c = 0; c < NCOL; c++)
                    outext[(size_t)row * NCOL + c] = Ls[tid * NCOL + c] - lse;
            }
        }
    }
}

// ---------------- launch ----------------
extern "C" void kernel_launch(void* const* d_in, const int* in_sizes, int n_in,
                              void* d_out, int out_size)
{
    const float* x    = (const float*)d_in[0];
    const float* degE = (const float*)d_in[1];
    const float* degV = (const float*)d_in[2];
    const float* W0   = (const float*)d_in[3];
    const float* b0   = (const float*)d_in[4];
    const float* Ws   = (const float*)d_in[5];
    const float* Wout = (const float*)d_in[6];
    const float* bout = (const float*)d_in[7];
    const int* vertex = (const int*)d_in[8];
    const int* edges  = (const int*)d_in[9];
    float* out = (float*)d_out;

    (void)in_sizes; (void)n_in; (void)out_size;

    const int GB = (N_V + 63) / 64;
    const int Q4 = NNZ_ / 4;

    // CSR/CSC build (bump allocation, no serial scans; int4 MLP on atomics)
    zero_cnt_k<<<(N_V + 255) / 256, 256>>>();
    hist_k<<<(Q4 + 255) / 256, 256>>>((const int4*)vertex, (const int4*)edges);
    alloc_k<<<(NE_ + N_V + 255) / 256, 256>>>(degE);
    build_adj_k<<<(Q4 + 255) / 256, 256>>>((const int4*)vertex, (const int4*)edges);

    // X = relu(x @ W0 + b0); X0 = X; Xh = half(X)
    gemm_k<128, 64, 0><<<GB, 256>>>(x, W0, b0, nullptr, 0.f, 0.f);

    for (int i = 0; i < NLAYER_; i++) {
        float beta = logf(0.5f / (float)(i + 1) + 1.0f);
        agg_ve_k<<<(NE_ + 7) / 8, 256>>>();
        agg_ev_k<<<(N_V + 7) / 8, 256>>>(degV);
        gemm_k<64, 64, 1><<<GB, 256>>>(nullptr, Ws + (size_t)i * NHID_ * NHID_,
                                       nullptr, nullptr, 1.0f - beta, beta);
    }

    // log_softmax(X @ Wout + bout)
    gemm_k<64, 40, 2><<<GB, 256>>>(nullptr, Wout, bout, out, 0.f, 0.f);
}

// round 6
// speedup vs baseline: 1.0528x; 1.0528x over previous
#include <cuda_runtime.h>
#include <math.h>

#define N_V    100000
#define NE_    20000
#define NNZ_   1600000
#define NFEAT_ 128
#define NHID_  64
#define NCLASS_ 40
#define NLAYER_ 4

// ---------------- device scratch (static, no allocation) ----------------
__device__ float g_X [N_V * NHID_];   // current features
__device__ float g_X0[N_V * NHID_];   // residual anchor
__device__ float g_Xe[NE_ * NHID_];   // edge features (pre-scaled by degE/count)
__device__ float g_escale[NE_];
__device__ int   g_cntE[NE_];
__device__ int   g_cntV[N_V];
__device__ int   g_lenE[NE_];
__device__ int   g_lenV[N_V];
__device__ int   g_offE[NE_];
__device__ int   g_offV[N_V];
__device__ int   g_curE;
__device__ int   g_curV;
__device__ int   g_adjE[NNZ_];        // members (vertex ids) per edge
__device__ int   g_adjV[NNZ_];        // incident edges per vertex

// ---------------- CSR build ----------------
__global__ void zero_cnt_k() {
    int i = blockIdx.x * blockDim.x + threadIdx.x;
    if (i < NE_) g_cntE[i] = 0;
    if (i < N_V) g_cntV[i] = 0;
    if (i == 0) { g_curE = 0; g_curV = 0; }
}

// 4 pairs per thread for MLP on the atomic chains
__global__ void hist_k(const int4* __restrict__ vertex4, const int4* __restrict__ edges4) {
    int i = blockIdx.x * blockDim.x + threadIdx.x;
    if (i < NNZ_ / 4) {
        int4 e = edges4[i];
        int4 v = vertex4[i];
        atomicAdd(&g_cntE[e.x], 1);
        atomicAdd(&g_cntE[e.y], 1);
        atomicAdd(&g_cntE[e.z], 1);
        atomicAdd(&g_cntE[e.w], 1);
        atomicAdd(&g_cntV[v.x], 1);
        atomicAdd(&g_cntV[v.y], 1);
        atomicAdd(&g_cntV[v.z], 1);
        atomicAdd(&g_cntV[v.w], 1);
    }
}

// warp-aggregated bump allocation of CSR offsets (segment order arbitrary but
// valid; per-segment sums are order-independent).
__global__ void alloc_k(const float* __restrict__ degE) {
    int i = blockIdx.x * blockDim.x + threadIdx.x;
    const int n = NE_ + N_V;
    if (i >= n) return;           // NE_ and n are multiples of 32
    int lane = threadIdx.x & 31;
    bool isE = (i < NE_);
    int c = isE ? g_cntE[i] : g_cntV[i - NE_];
    int inc = c;
    #pragma unroll
    for (int o = 1; o < 32; o <<= 1) {
        int t = __shfl_up_sync(0xffffffffu, inc, o);
        if (lane >= o) inc += t;
    }
    int base = 0;
    if (lane == 31)
        base = atomicAdd(isE ? &g_curE : &g_curV, inc);
    base = __shfl_sync(0xffffffffu, base, 31);
    int off = base + inc - c;
    if (isE) {
        g_offE[i] = off;
        g_lenE[i] = c;
        g_escale[i] = degE[i] / fmaxf((float)c, 1.0f);
        g_cntE[i] = 0;
    } else {
        g_offV[i - NE_] = off;
        g_lenV[i - NE_] = c;
        g_cntV[i - NE_] = 0;
    }
}

__global__ void build_adj_k(const int4* __restrict__ vertex4, const int4* __restrict__ edges4) {
    int i = blockIdx.x * blockDim.x + threadIdx.x;
    if (i < NNZ_ / 4) {
        int4 v = vertex4[i];
        int4 e = edges4[i];
        int oe0 = g_offE[e.x], oe1 = g_offE[e.y], oe2 = g_offE[e.z], oe3 = g_offE[e.w];
        int ov0 = g_offV[v.x], ov1 = g_offV[v.y], ov2 = g_offV[v.z], ov3 = g_offV[v.w];
        int pe0 = oe0 + atomicAdd(&g_cntE[e.x], 1);
        int pe1 = oe1 + atomicAdd(&g_cntE[e.y], 1);
        int pe2 = oe2 + atomicAdd(&g_cntE[e.z], 1);
        int pe3 = oe3 + atomicAdd(&g_cntE[e.w], 1);
        int pv0 = ov0 + atomicAdd(&g_cntV[v.x], 1);
        int pv1 = ov1 + atomicAdd(&g_cntV[v.y], 1);
        int pv2 = ov2 + atomicAdd(&g_cntV[v.z], 1);
        int pv3 = ov3 + atomicAdd(&g_cntV[v.w], 1);
        g_adjE[pe0] = v.x; g_adjE[pe1] = v.y; g_adjE[pe2] = v.z; g_adjE[pe3] = v.w;
        g_adjV[pv0] = e.x; g_adjV[pv1] = e.y; g_adjV[pv2] = e.z; g_adjV[pv3] = e.w;
    }
}

// ---------------- vertex -> edge mean (warp per edge, float2 lanes) ----------------
__global__ void __launch_bounds__(256) agg_ve_k() {
    int e = blockIdx.x * 8 + (threadIdx.x >> 5);
    if (e >= NE_) return;
    int lane = threadIdx.x & 31;
    int beg = g_offE[e], len = g_lenE[e];
    float ax = 0.f, ay = 0.f;
    const float* __restrict__ X = g_X;
    int j = 0;
    for (; j + 8 <= len; j += 8) {
        int i0 = g_adjE[beg + j + 0], i1 = g_adjE[beg + j + 1];
        int i2 = g_adjE[beg + j + 2], i3 = g_adjE[beg + j + 3];
        int i4 = g_adjE[beg + j + 4], i5 = g_adjE[beg + j + 5];
        int i6 = g_adjE[beg + j + 6], i7 = g_adjE[beg + j + 7];
        float2 t0 = __ldg((const float2*)&X[i0 * NHID_ + lane * 2]);
        float2 t1 = __ldg((const float2*)&X[i1 * NHID_ + lane * 2]);
        float2 t2 = __ldg((const float2*)&X[i2 * NHID_ + lane * 2]);
        float2 t3 = __ldg((const float2*)&X[i3 * NHID_ + lane * 2]);
        float2 t4 = __ldg((const float2*)&X[i4 * NHID_ + lane * 2]);
        float2 t5 = __ldg((const float2*)&X[i5 * NHID_ + lane * 2]);
        float2 t6 = __ldg((const float2*)&X[i6 * NHID_ + lane * 2]);
        float2 t7 = __ldg((const float2*)&X[i7 * NHID_ + lane * 2]);
        ax += ((t0.x + t1.x) + (t2.x + t3.x)) + ((t4.x + t5.x) + (t6.x + t7.x));
        ay += ((t0.y + t1.y) + (t2.y + t3.y)) + ((t4.y + t5.y) + (t6.y + t7.y));
    }
    for (; j < len; j++) {
        int v = g_adjE[beg + j];
        float2 t = __ldg((const float2*)&X[v * NHID_ + lane * 2]);
        ax += t.x; ay += t.y;
    }
    float s = g_escale[e];
    float2 r; r.x = ax * s; r.y = ay * s;
    *(float2*)&g_Xe[e * NHID_ + lane * 2] = r;
}

// ---------------- edge -> vertex sum (warp per vertex, float2 lanes),
//                  fused *degV, L2 norm (shuffle-only), alpha-mix ----------------
__global__ void __launch_bounds__(256) agg_ev_k(const float* __restrict__ degV) {
    int v = blockIdx.x * 8 + (threadIdx.x >> 5);
    if (v >= N_V) return;
    int lane = threadIdx.x & 31;
    int beg = g_offV[v], len = g_lenV[v];
    float ax = 0.f, ay = 0.f;
    const float* __restrict__ Xe = g_Xe;
    int j = 0;
    for (; j + 8 <= len; j += 8) {
        int e0 = g_adjV[beg + j + 0], e1 = g_adjV[beg + j + 1];
        int e2 = g_adjV[beg + j + 2], e3 = g_adjV[beg + j + 3];
        int e4 = g_adjV[beg + j + 4], e5 = g_adjV[beg + j + 5];
        int e6 = g_adjV[beg + j + 6], e7 = g_adjV[beg + j + 7];
        float2 t0 = __ldg((const float2*)&Xe[e0 * NHID_ + lane * 2]);
        float2 t1 = __ldg((const float2*)&Xe[e1 * NHID_ + lane * 2]);
        float2 t2 = __ldg((const float2*)&Xe[e2 * NHID_ + lane * 2]);
        float2 t3 = __ldg((const float2*)&Xe[e3 * NHID_ + lane * 2]);
        float2 t4 = __ldg((const float2*)&Xe[e4 * NHID_ + lane * 2]);
        float2 t5 = __ldg((const float2*)&Xe[e5 * NHID_ + lane * 2]);
        float2 t6 = __ldg((const float2*)&Xe[e6 * NHID_ + lane * 2]);
        float2 t7 = __ldg((const float2*)&Xe[e7 * NHID_ + lane * 2]);
        ax += ((t0.x + t1.x) + (t2.x + t3.x)) + ((t4.x + t5.x) + (t6.x + t7.x));
        ay += ((t0.y + t1.y) + (t2.y + t3.y)) + ((t4.y + t5.y) + (t6.y + t7.y));
    }
    for (; j < len; j++) {
        int e = g_adjV[beg + j];
        float2 t = __ldg((const float2*)&Xe[e * NHID_ + lane * 2]);
        ax += t.x; ay += t.y;
    }
    float dv = __ldg(&degV[v]);
    ax *= dv; ay *= dv;
    float ss = ax * ax + ay * ay;
    #pragma unroll
    for (int o = 16; o; o >>= 1) ss += __shfl_xor_sync(0xffffffffu, ss, o);
    float scale = (ss > 0.f) ? rsqrtf(ss) : 0.f;
    float2 x0 = *(const float2*)&g_X0[(size_t)v * NHID_ + lane * 2];
    float2 r;
    r.x = 0.9f * ax * scale + 0.1f * x0.x;
    r.y = 0.9f * ay * scale + 0.1f * x0.y;
    *(float2*)&g_X[(size_t)v * NHID_ + lane * 2] = r;
}

// ---------------- tiled GEMM: 64-row tile, 128 threads, 4x8 micro-tile ----------------
// MODE 0: X = relu(A@W + b), also copy to X0.   (A = external x, K=128, NCOL=64)
// MODE 1: X = relu(c0*Xi + c1*(Xi@W)), in-place. (K=NCOL=64)
// MODE 2: out = log_softmax(g_X@W + b).          (K=64, NCOL=40)
template <int K, int NCOL, int MODE>
__global__ void __launch_bounds__(128) gemm_k(
    const float* __restrict__ Aext, const float* __restrict__ W,
    const float* __restrict__ bias, float* __restrict__ outext,
    float c0, float c1)
{
    constexpr int KC = 64;
    constexpr int KP = KC + 4;
    constexpr int NP = (NCOL + 7) & ~3;   // 68 / 44 (row stride stays 16B-aligned)
    __shared__ float As[64 * KP];
    __shared__ float Wsm[KC * NP];
    __shared__ float Ls[(MODE == 2) ? 64 * NCOL : 1];

    const float* A = (MODE == 0) ? Aext : g_X;
    const int M = N_V;
    int tid = threadIdx.x;
    int row0 = blockIdx.x * 64;
    int tx = tid & 7;        // col group: 8 columns
    int ty = tid >> 3;       // 0..15: 4 rows each
    bool active = (NCOL == 64) || (tx * 8 < NCOL);

    float acc[4][8] = {};

    for (int kc = 0; kc < K; kc += KC) {
        for (int idx = tid; idx < KC * (NCOL / 4); idx += 128) {
            int k = idx / (NCOL / 4), c4 = idx - k * (NCOL / 4);
            *(float4*)&Wsm[k * NP + c4 * 4] = *(const float4*)&W[(kc + k) * NCOL + c4 * 4];
        }
        for (int idx = tid; idx < 64 * (KC / 4); idx += 128) {
            int r = idx / (KC / 4), k4 = idx - r * (KC / 4);
            int row = row0 + r;
            float4 v = make_float4(0.f, 0.f, 0.f, 0.f);
            if (row < M) v = *(const float4*)&A[(size_t)row * K + kc + k4 * 4];
            *(float4*)&As[r * KP + k4 * 4] = v;
        }
        __syncthreads();
        if (active) {
            #pragma unroll 4
            for (int k = 0; k < KC; k++) {
                float4 w0 = *(const float4*)&Wsm[k * NP + tx * 8];
                float4 w1 = *(const float4*)&Wsm[k * NP + tx * 8 + 4];
                #pragma unroll
                for (int i = 0; i < 4; i++) {
                    float a = As[(ty * 4 + i) * KP + k];
                    acc[i][0] += a * w0.x; acc[i][1] += a * w0.y;
                    acc[i][2] += a * w0.z; acc[i][3] += a * w0.w;
                    acc[i][4] += a * w1.x; acc[i][5] += a * w1.y;
                    acc[i][6] += a * w1.z; acc[i][7] += a * w1.w;
                }
            }
        }
        __syncthreads();
    }

    if (MODE == 0) {
        float4 ba = *(const float4*)&bias[tx * 8];
        float4 bb = *(const float4*)&bias[tx * 8 + 4];
        #pragma unroll
        for (int i = 0; i < 4; i++) {
            int row = row0 + ty * 4 + i;
            if (row < M) {
                float4 ra, rb;
                ra.x = fmaxf(acc[i][0] + ba.x, 0.f);
                ra.y = fmaxf(acc[i][1] + ba.y, 0.f);
                ra.z = fmaxf(acc[i][2] + ba.z, 0.f);
                ra.w = fmaxf(acc[i][3] + ba.w, 0.f);
                rb.x = fmaxf(acc[i][4] + bb.x, 0.f);
                rb.y = fmaxf(acc[i][5] + bb.y, 0.f);
                rb.z = fmaxf(acc[i][6] + bb.z, 0.f);
                rb.w = fmaxf(acc[i][7] + bb.w, 0.f);
                *(float4*)&g_X [(size_t)row * NHID_ + tx * 8]     = ra;
                *(float4*)&g_X [(size_t)row * NHID_ + tx * 8 + 4] = rb;
                *(float4*)&g_X0[(size_t)row * NHID_ + tx * 8]     = ra;
                *(float4*)&g_X0[(size_t)row * NHID_ + tx * 8 + 4] = rb;
            }
        }
    } else if (MODE == 1) {
        #pragma unroll
        for (int i = 0; i < 4; i++) {
            int r = ty * 4 + i;
            int row = row0 + r;
            if (row < M) {
                float4 ra, rb;
                ra.x = fmaxf(c0 * As[r * KP + tx * 8 + 0] + c1 * acc[i][0], 0.f);
                ra.y = fmaxf(c0 * As[r * KP + tx * 8 + 1] + c1 * acc[i][1], 0.f);
                ra.z = fmaxf(c0 * As[r * KP + tx * 8 + 2] + c1 * acc[i][2], 0.f);
                ra.w = fmaxf(c0 * As[r * KP + tx * 8 + 3] + c1 * acc[i][3], 0.f);
                rb.x = fmaxf(c0 * As[r * KP + tx * 8 + 4] + c1 * acc[i][4], 0.f);
                rb.y = fmaxf(c0 * As[r * KP + tx * 8 + 5] + c1 * acc[i][5], 0.f);
                rb.z = fmaxf(c0 * As[r * KP + tx * 8 + 6] + c1 * acc[i][6], 0.f);
                rb.w = fmaxf(c0 * As[r * KP + tx * 8 + 7] + c1 * acc[i][7], 0.f);
                *(float4*)&g_X[(size_t)row * NHID_ + tx * 8]     = ra;
                *(float4*)&g_X[(size_t)row * NHID_ + tx * 8 + 4] = rb;
            }
        }
    } else {  // MODE 2: logits + fused log_softmax
        if (active) {
            #pragma unroll
            for (int i = 0; i < 4; i++) {
                int r = ty * 4 + i;
                #pragma unroll
                for (int j = 0; j < 8; j++)
                    Ls[r * NCOL + tx * 8 + j] = acc[i][j] + __ldg(bias + tx * 8 + j);
            }
        }
        __syncthreads();
        if (tid < 64) {
            int row = row0 + tid;
            if (row < M) {
                float mx = -1e30f;
                #pragma unroll
                for (int c = 0; c < NCOL; c++) mx = fmaxf(mx, Ls[tid * NCOL + c]);
                float s = 0.f;
                #pragma unroll
                for (int c = 0; c < NCOL; c++) s += __expf(Ls[tid * NCOL + c] - mx);
                float lse = mx + __logf(s);
                #pragma unroll
                for (int c = 0; c < NCOL; c++)
                    outext[(size_t)row * NCOL + c] = Ls[tid * NCOL + c] - lse;
            }
        }
    }
}

// ---------------- launch ----------------
extern "C" void kernel_launch(void* const* d_in, const int* in_sizes, int n_in,
                              void* d_out, int out_size)
{
    const float* x    = (const float*)d_in[0];
    const float* degE = (const float*)d_in[1];
    const float* degV = (const float*)d_in[2];
    const float* W0   = (const float*)d_in[3];
    const float* b0   = (const float*)d_in[4];
    const float* Ws   = (const float*)d_in[5];
    const float* Wout = (const float*)d_in[6];
    const float* bout = (const float*)d_in[7];
    const int* vertex = (const int*)d_in[8];
    const int* edges  = (const int*)d_in[9];
    float* out = (float*)d_out;

    (void)in_sizes; (void)n_in; (void)out_size;

    const int GB = (N_V + 63) / 64;
    const int Q4 = NNZ_ / 4;

    // CSR/CSC build (bump allocation, no serial scans; int4 MLP on atomics)
    zero_cnt_k<<<(N_V + 255) / 256, 256>>>();
    hist_k<<<(Q4 + 255) / 256, 256>>>((const int4*)vertex, (const int4*)edges);
    alloc_k<<<(NE_ + N_V + 255) / 256, 256>>>(degE);
    build_adj_k<<<(Q4 + 255) / 256, 256>>>((const int4*)vertex, (const int4*)edges);

    // X = relu(x @ W0 + b0); X0 = X
    gemm_k<128, 64, 0><<<GB, 128>>>(x, W0, b0, nullptr, 0.f, 0.f);

    for (int i = 0; i < NLAYER_; i++) {
        float beta = logf(0.5f / (float)(i + 1) + 1.0f);
        agg_ve_k<<<(NE_ + 7) / 8, 256>>>();
        agg_ev_k<<<(N_V + 7) / 8, 256>>>(degV);
        gemm_k<64, 64, 1><<<GB, 128>>>(nullptr, Ws + (size_t)i * NHID_ * NHID_,
                                       nullptr, nullptr, 1.0f - beta, beta);
    }

    // log_softmax(X @ Wout + bout)
    gemm_k<64, 40, 2><<<GB, 128>>>(nullptr, Wout, bout, out, 0.f, 0.f);
}